// round 8
// baseline (speedup 1.0000x reference)
#include <cuda_runtime.h>
#include <cstdint>

// QCNN_58025008169535
// x: [32,128,128,3] f32, w: [4,4,3] f32 -> out: [32, 127*127, 4] f32
//
// Tensor-core formulation: per patch, amp = U psi is a real 32x32 GEMV with
// W = [[ReU, -ImU],[ImU, ReU]], v = [Re psi; Im psi]. Batched over patches:
// Amp[32xN] = W[32x32] V[32xN] via mma.sync.m16n8k8.tf32, with 3-pass
// hi/lo precision split (Ahi*Bhi + Ahi*Blo + Alo*Bhi).

#define DIM 16
#define NL 4
#define NQ 4

static constexpr int Bc = 32, Hc = 128, Wc = 128;
static constexpr int PHc = Hc - 1, PWc = Wc - 1;
static constexpr int Pc = PHc * PWc;          // 16129
static constexpr int TOTALc = Bc * Pc;        // 516128
static constexpr int WTOT = TOTALc / 32;      // 16129 warp-iterations
static constexpr int TITER = 8;               // warp-iters per warp
static constexpr int NWARP = 4;               // warps per block
static constexpr int NBLK = (WTOT + NWARP * TITER - 1) / (NWARP * TITER);  // 505

typedef unsigned int uint;

// W split: Whi = tf32(W), Wlo = tf32(W - Whi). Row-major 32x32.
__device__ float g_Whi[32 * 32];
__device__ float g_Wlo[32 * 32];

__device__ __forceinline__ float2 cmul(float2 a, float2 b) {
    return make_float2(fmaf(a.x, b.x, -a.y * b.y), fmaf(a.x, b.y, a.y * b.x));
}
__device__ __forceinline__ float2 cadd(float2 a, float2 b) {
    return make_float2(a.x + b.x, a.y + b.y);
}
__device__ __forceinline__ uint tf32cvt(float f) {
    uint r; asm("cvt.rna.tf32.f32 %0, %1;" : "=r"(r) : "f"(f)); return r;
}

#define MMA_TF32(C0, C1, C2, C3, A0, A1, A2, A3, B0, B1)                      \
    asm volatile(                                                             \
        "mma.sync.aligned.m16n8k8.row.col.f32.tf32.tf32.f32 "                 \
        "{%0,%1,%2,%3}, {%4,%5,%6,%7}, {%8,%9}, {%0,%1,%2,%3};"               \
        : "+f"(C0), "+f"(C1), "+f"(C2), "+f"(C3)                              \
        : "r"(A0), "r"(A1), "r"(A2), "r"(A3), "r"(B0), "r"(B1))

// ---------------------------------------------------------------------------
// Kernel 1 (256 threads): build U, emit W as tf32 hi/lo split.
// ---------------------------------------------------------------------------
__global__ void k_build_U(const float* __restrict__ w) {
    __shared__ float2 sg[16][4];
    __shared__ float2 sM[4][DIM][DIM];
    __shared__ float2 sT[2][DIM][DIM];

    int tid = threadIdx.x;

    if (tid < 16) {
        float wx = w[tid * 3 + 0];
        float wy = w[tid * 3 + 1];
        float wz = w[tid * 3 + 2];
        float cx, sx, cy, sy, cz, sz;
        sincosf(0.5f * wx, &sx, &cx);
        sincosf(0.5f * wy, &sy, &cy);
        sincosf(0.5f * wz, &sz, &cz);
        float2 m00 = make_float2(cy * cx,  sy * sx);
        float2 m01 = make_float2(-sy * cx, -cy * sx);
        float2 m10 = make_float2(sy * cx,  -cy * sx);
        float2 m11 = make_float2(cy * cx,  -sy * sx);
        float2 e0 = make_float2(cz, -sz);
        float2 e1 = make_float2(cz,  sz);
        sg[tid][0] = cmul(e0, m00);
        sg[tid][1] = cmul(e0, m01);
        sg[tid][2] = cmul(e1, m10);
        sg[tid][3] = cmul(e1, m11);
    }
    __syncthreads();

#pragma unroll
    for (int r = 0; r < 4; r++) {
        int e = tid + 256 * r;
        int h = e >> 8;
        int st = e & 255;
        int s = st >> 4, t = st & 15;
        float2 prod = make_float2(1.f, 0.f);
#pragma unroll
        for (int q = 0; q < NQ; q++) {
            int sb = (s >> (3 - q)) & 1;
            int tb = (t >> (3 - q)) & 1;
            prod = cmul(prod, sg[h * 4 + q][sb * 2 + tb]);
        }
        bool neg = (((s & 12) == 12) ^ ((s & 3) == 3)) ^ ((s & 6) == 6);
        if (neg) { prod.x = -prod.x; prod.y = -prod.y; }
        sM[h][s][t] = prod;
    }
    __syncthreads();

    {
        int s = tid >> 4, t = tid & 15;
        float2 a1 = make_float2(0.f, 0.f);
        float2 a2 = make_float2(0.f, 0.f);
#pragma unroll
        for (int k = 0; k < DIM; k++) {
            a1 = cadd(a1, cmul(sM[1][s][k], sM[0][k][t]));
            a2 = cadd(a2, cmul(sM[3][s][k], sM[2][k][t]));
        }
        sT[0][s][t] = a1;
        sT[1][s][t] = a2;
    }
    __syncthreads();

    {
        int s = tid >> 4, t = tid & 15;
        float2 u = make_float2(0.f, 0.f);
#pragma unroll
        for (int k = 0; k < DIM; k++)
            u = cadd(u, cmul(sT[1][s][k], sT[0][k][t]));

        // W = [[Re, -Im],[Im, Re]], hi/lo split
        float vals[4] = {u.x, -u.y, u.y, u.x};
        int   idxs[4] = {s * 32 + t, s * 32 + 16 + t,
                         (16 + s) * 32 + t, (16 + s) * 32 + 16 + t};
#pragma unroll
        for (int q = 0; q < 4; q++) {
            float f  = vals[q];
            uint  hb = tf32cvt(f);
            float hf = __uint_as_float(hb);
            uint  lb = tf32cvt(f - hf);
            g_Whi[idxs[q]] = hf;
            g_Wlo[idxs[q]] = __uint_as_float(lb);
        }
    }
}

// ---------------------------------------------------------------------------
// Kernel 2: tensor-core batched matvec. Each warp-iteration = 32 patches:
// lane encodes patch (Wi*32 + lane) -> v to smem; 4 n-tiles of 8 patches:
// 24 mma each; epilogue: prob, Walsh partials, shfl-bfly reduce, store.
// ---------------------------------------------------------------------------
__global__ void __launch_bounds__(128)
k_qcnn(const float* __restrict__ x, float* __restrict__ out) {
    __shared__ float v_sm[NWARP][32][36];   // [warp][patch][k], pad 36

    int tid  = threadIdx.x;
    int wrp  = tid >> 5;
    int lane = tid & 31;
    int g    = lane >> 2;     // group id (row within fragments)
    int mm   = lane & 3;      // thread-in-group (col within fragments)

    // --- A fragments: Whi/Wlo, 2 M-tiles x 4 K-tiles x 4 regs ---
    uint Ah[2][4][4], Al[2][4][4];
    {
        const uint* whi = (const uint*)g_Whi;
        const uint* wlo = (const uint*)g_Wlo;
#pragma unroll
        for (int m = 0; m < 2; m++)
#pragma unroll
            for (int t = 0; t < 4; t++) {
                int r0 = m * 16 + g, r1 = r0 + 8;
                int c0 = t * 8 + mm, c1 = c0 + 4;
                Ah[m][t][0] = whi[r0 * 32 + c0];
                Ah[m][t][1] = whi[r1 * 32 + c0];
                Ah[m][t][2] = whi[r0 * 32 + c1];
                Ah[m][t][3] = whi[r1 * 32 + c1];
                Al[m][t][0] = wlo[r0 * 32 + c0];
                Al[m][t][1] = wlo[r1 * 32 + c0];
                Al[m][t][2] = wlo[r0 * 32 + c1];
                Al[m][t][3] = wlo[r1 * 32 + c1];
            }
    }

    // Walsh sign constants for this thread's states (g and g+8)
    float s4 = (lane & 16) ? -1.f : 1.f;   // bit2 of state (qubit 1)
    float s2 = (lane & 8)  ? -1.f : 1.f;   // bit1 (qubit 2)
    float s1 = (lane & 4)  ? -1.f : 1.f;   // bit0 (qubit 3)

    float4* out4 = reinterpret_cast<float4*>(out);

    for (int it = 0; it < TITER; it++) {
        int Wi = (blockIdx.x * NWARP + wrp) * TITER + it;
        if (Wi >= WTOT) break;

        // ---- encode patch Wi*32 + lane ----
        {
            int idx = Wi * 32 + lane;
            int b  = idx / Pc;
            int p  = idx - b * Pc;
            int ph = p / PWc;
            int pw = p - ph * PWc;

            float  cth[NQ];
            float2 eph[NQ];
#pragma unroll
            for (int n = 0; n < NQ; n++) {
                int dy = n >> 1, dx = n & 1;
                const float* px = x + ((((b * Hc) + (ph + dy)) * Wc + (pw + dx)) * 3);
                float l1 = px[1];
                float l2 = px[2];
                float sb, cb, sp, cp;
                __sincosf(1.57079632679489662f * l1, &sb, &cb);
                __sincosf(3.14159265358979323f * l2, &sp, &cp);
                cth[n] = cb;
                eph[n] = make_float2(sb * cp, sb * sp);
            }
            float2 ab[4], cd[4];
            ab[0] = make_float2(cth[0] * cth[1], 0.f);
            ab[1] = make_float2(cth[0] * eph[1].x, cth[0] * eph[1].y);
            ab[2] = make_float2(eph[0].x * cth[1], eph[0].y * cth[1]);
            ab[3] = cmul(eph[0], eph[1]);
            cd[0] = make_float2(cth[2] * cth[3], 0.f);
            cd[1] = make_float2(cth[2] * eph[3].x, cth[2] * eph[3].y);
            cd[2] = make_float2(eph[2].x * cth[3], eph[2].y * cth[3]);
            cd[3] = cmul(eph[2], eph[3]);

            float2 psi[16];
#pragma unroll
            for (int i = 0; i < 4; i++)
#pragma unroll
                for (int j = 0; j < 4; j++)
                    psi[i * 4 + j] = cmul(ab[i], cd[j]);

            // v = [Re psi (k 0-15); Im psi (k 16-31)], STS.128
            float4* vrow = reinterpret_cast<float4*>(&v_sm[wrp][lane][0]);
#pragma unroll
            for (int q = 0; q < 4; q++)
                vrow[q] = make_float4(psi[4*q].x, psi[4*q+1].x,
                                      psi[4*q+2].x, psi[4*q+3].x);
#pragma unroll
            for (int q = 0; q < 4; q++)
                vrow[4 + q] = make_float4(psi[4*q].y, psi[4*q+1].y,
                                          psi[4*q+2].y, psi[4*q+3].y);
        }
        __syncwarp();

        // ---- 4 n-tiles of 8 patches ----
#pragma unroll
        for (int nt = 0; nt < 4; nt++) {
            float c0 = 0.f, c1 = 0.f, c2 = 0.f, c3 = 0.f;   // Re rows
            float d0 = 0.f, d1 = 0.f, d2 = 0.f, d3 = 0.f;   // Im rows

            const float* vb = &v_sm[wrp][nt * 8 + g][0];
#pragma unroll
            for (int t = 0; t < 4; t++) {
                float f0 = vb[t * 8 + mm];
                float f1 = vb[t * 8 + mm + 4];
                uint bh0 = tf32cvt(f0);
                uint bh1 = tf32cvt(f1);
                uint bl0 = tf32cvt(f0 - __uint_as_float(bh0));
                uint bl1 = tf32cvt(f1 - __uint_as_float(bh1));

                MMA_TF32(c0, c1, c2, c3,
                         Ah[0][t][0], Ah[0][t][1], Ah[0][t][2], Ah[0][t][3],
                         bh0, bh1);
                MMA_TF32(c0, c1, c2, c3,
                         Ah[0][t][0], Ah[0][t][1], Ah[0][t][2], Ah[0][t][3],
                         bl0, bl1);
                MMA_TF32(c0, c1, c2, c3,
                         Al[0][t][0], Al[0][t][1], Al[0][t][2], Al[0][t][3],
                         bh0, bh1);
                MMA_TF32(d0, d1, d2, d3,
                         Ah[1][t][0], Ah[1][t][1], Ah[1][t][2], Ah[1][t][3],
                         bh0, bh1);
                MMA_TF32(d0, d1, d2, d3,
                         Ah[1][t][0], Ah[1][t][1], Ah[1][t][2], Ah[1][t][3],
                         bl0, bl1);
                MMA_TF32(d0, d1, d2, d3,
                         Al[1][t][0], Al[1][t][1], Al[1][t][2], Al[1][t][3],
                         bh0, bh1);
            }

            // ---- epilogue: probs -> Walsh partials -> bfly reduce ----
            // thread holds: col j0 = 2*mm: (state g: c0,d0), (state g+8: c2,d2)
            //               col j1 = 2*mm+1: (c1,d1), (c3,d3)
            float pa0 = fmaf(c0, c0, d0 * d0);
            float pb0 = fmaf(c2, c2, d2 * d2);
            float pa1 = fmaf(c1, c1, d1 * d1);
            float pb1 = fmaf(c3, c3, d3 * d3);

            float sum0 = pa0 + pb0, sum1 = pa1 + pb1;
            float z0_0 = pa0 - pb0,  z0_1 = pa1 - pb1;
            float z1_0 = s4 * sum0,  z1_1 = s4 * sum1;
            float z2_0 = s2 * sum0,  z2_1 = s2 * sum1;
            float z3_0 = s1 * sum0,  z3_1 = s1 * sum1;

#pragma unroll
            for (int mask = 4; mask <= 16; mask <<= 1) {
                z0_0 += __shfl_xor_sync(0xffffffffu, z0_0, mask);
                z1_0 += __shfl_xor_sync(0xffffffffu, z1_0, mask);
                z2_0 += __shfl_xor_sync(0xffffffffu, z2_0, mask);
                z3_0 += __shfl_xor_sync(0xffffffffu, z3_0, mask);
                z0_1 += __shfl_xor_sync(0xffffffffu, z0_1, mask);
                z1_1 += __shfl_xor_sync(0xffffffffu, z1_1, mask);
                z2_1 += __shfl_xor_sync(0xffffffffu, z2_1, mask);
                z3_1 += __shfl_xor_sync(0xffffffffu, z3_1, mask);
            }

            if (g == 0) {
                int pbase = Wi * 32 + nt * 8 + 2 * mm;
                out4[pbase]     = make_float4(z0_0, z1_0, z2_0, z3_0);
                out4[pbase + 1] = make_float4(z0_1, z1_1, z2_1, z3_1);
            }
        }
        __syncwarp();
    }
}

extern "C" void kernel_launch(void* const* d_in, const int* in_sizes, int n_in,
                              void* d_out, int out_size) {
    const float* x = (const float*)d_in[0];
    const float* w = (const float*)d_in[1];
    float* out = (float*)d_out;

    k_build_U<<<1, 256>>>(w);
    k_qcnn<<<NBLK, NWARP * 32>>>(x, out);
}

// round 9
// speedup vs baseline: 1.1397x; 1.1397x over previous
#include <cuda_runtime.h>
#include <cstdint>

// QCNN_58025008169535
// x: [32,128,128,3] f32, w: [4,4,3] f32 -> out: [32, 127*127, 4] f32
//
// Tensor-core formulation. amp_re = A0 v, amp_im = A0 v', where
// A0 = [ReU | -ImU] (16x32), v = [Re psi; Im psi], v' = [Im psi; -Re psi].
// v' B-fragments are v's fragments with k-tiles rotated by 2 and sign-
// flipped for the rotated-in Re half -> no second A fragment set needed.
// 3-pass tf32 hi/lo split: Ahi*Bhi + Ahi*Blo + Alo*Bhi.

#define DIM 16
#define NL 4
#define NQ 4

static constexpr int Bc = 32, Hc = 128, Wc = 128;
static constexpr int PHc = Hc - 1, PWc = Wc - 1;
static constexpr int Pc = PHc * PWc;          // 16129
static constexpr int TOTALc = Bc * Pc;        // 516128
static constexpr int WTOT = TOTALc / 32;      // 16129 warp-iterations
static constexpr int TITER = 2;               // warp-iters per warp
static constexpr int NWARP = 4;               // warps per block
static constexpr int NBLK = (WTOT + NWARP * TITER - 1) / (NWARP * TITER);  // 2017

typedef unsigned int uint;

// W split: Whi = tf32(W), Wlo = tf32(W - Whi). Row-major 32x32 (top 16 rows used).
__device__ float g_Whi[32 * 32];
__device__ float g_Wlo[32 * 32];

__device__ __forceinline__ float2 cmul(float2 a, float2 b) {
    return make_float2(fmaf(a.x, b.x, -a.y * b.y), fmaf(a.x, b.y, a.y * b.x));
}
__device__ __forceinline__ float2 cadd(float2 a, float2 b) {
    return make_float2(a.x + b.x, a.y + b.y);
}
__device__ __forceinline__ uint tf32cvt(float f) {
    uint r; asm("cvt.rna.tf32.f32 %0, %1;" : "=r"(r) : "f"(f)); return r;
}

#define MMA_TF32(C0, C1, C2, C3, A0, A1, A2, A3, B0, B1)                      \
    asm volatile(                                                             \
        "mma.sync.aligned.m16n8k8.row.col.f32.tf32.tf32.f32 "                 \
        "{%0,%1,%2,%3}, {%4,%5,%6,%7}, {%8,%9}, {%0,%1,%2,%3};"               \
        : "+f"(C0), "+f"(C1), "+f"(C2), "+f"(C3)                              \
        : "r"(A0), "r"(A1), "r"(A2), "r"(A3), "r"(B0), "r"(B1))

// ---------------------------------------------------------------------------
// Kernel 1 (256 threads): build U, emit W as tf32 hi/lo split.
// ---------------------------------------------------------------------------
__global__ void k_build_U(const float* __restrict__ w) {
    __shared__ float2 sg[16][4];
    __shared__ float2 sM[4][DIM][DIM];
    __shared__ float2 sT[2][DIM][DIM];

    int tid = threadIdx.x;

    if (tid < 16) {
        float wx = w[tid * 3 + 0];
        float wy = w[tid * 3 + 1];
        float wz = w[tid * 3 + 2];
        float cx, sx, cy, sy, cz, sz;
        sincosf(0.5f * wx, &sx, &cx);
        sincosf(0.5f * wy, &sy, &cy);
        sincosf(0.5f * wz, &sz, &cz);
        float2 m00 = make_float2(cy * cx,  sy * sx);
        float2 m01 = make_float2(-sy * cx, -cy * sx);
        float2 m10 = make_float2(sy * cx,  -cy * sx);
        float2 m11 = make_float2(cy * cx,  -sy * sx);
        float2 e0 = make_float2(cz, -sz);
        float2 e1 = make_float2(cz,  sz);
        sg[tid][0] = cmul(e0, m00);
        sg[tid][1] = cmul(e0, m01);
        sg[tid][2] = cmul(e1, m10);
        sg[tid][3] = cmul(e1, m11);
    }
    __syncthreads();

#pragma unroll
    for (int r = 0; r < 4; r++) {
        int e = tid + 256 * r;
        int h = e >> 8;
        int st = e & 255;
        int s = st >> 4, t = st & 15;
        float2 prod = make_float2(1.f, 0.f);
#pragma unroll
        for (int q = 0; q < NQ; q++) {
            int sb = (s >> (3 - q)) & 1;
            int tb = (t >> (3 - q)) & 1;
            prod = cmul(prod, sg[h * 4 + q][sb * 2 + tb]);
        }
        bool neg = (((s & 12) == 12) ^ ((s & 3) == 3)) ^ ((s & 6) == 6);
        if (neg) { prod.x = -prod.x; prod.y = -prod.y; }
        sM[h][s][t] = prod;
    }
    __syncthreads();

    {
        int s = tid >> 4, t = tid & 15;
        float2 a1 = make_float2(0.f, 0.f);
        float2 a2 = make_float2(0.f, 0.f);
#pragma unroll
        for (int k = 0; k < DIM; k++) {
            a1 = cadd(a1, cmul(sM[1][s][k], sM[0][k][t]));
            a2 = cadd(a2, cmul(sM[3][s][k], sM[2][k][t]));
        }
        sT[0][s][t] = a1;
        sT[1][s][t] = a2;
    }
    __syncthreads();

    {
        int s = tid >> 4, t = tid & 15;
        float2 u = make_float2(0.f, 0.f);
#pragma unroll
        for (int k = 0; k < DIM; k++)
            u = cadd(u, cmul(sT[1][s][k], sT[0][k][t]));

        // W = [[Re, -Im],[Im, Re]], hi/lo split (bottom half unused but kept)
        float vals[4] = {u.x, -u.y, u.y, u.x};
        int   idxs[4] = {s * 32 + t, s * 32 + 16 + t,
                         (16 + s) * 32 + t, (16 + s) * 32 + 16 + t};
#pragma unroll
        for (int q = 0; q < 4; q++) {
            float f  = vals[q];
            uint  hb = tf32cvt(f);
            float hf = __uint_as_float(hb);
            uint  lb = tf32cvt(f - hf);
            g_Whi[idxs[q]] = hf;
            g_Wlo[idxs[q]] = __uint_as_float(lb);
        }
    }
}

// ---------------------------------------------------------------------------
// Kernel 2: tensor-core batched matvec, single A-fragment set.
// ---------------------------------------------------------------------------
__global__ void __launch_bounds__(128)
k_qcnn(const float* __restrict__ x, float* __restrict__ out) {
    __shared__ float v_sm[NWARP][32][36];   // [warp][patch][k], pad 36

    int tid  = threadIdx.x;
    int wrp  = tid >> 5;
    int lane = tid & 31;
    int g    = lane >> 2;     // fragment row group
    int mm   = lane & 3;      // fragment col-in-group

    // --- A fragments: top 16 rows of Whi/Wlo, 4 K-tiles x 4 regs ---
    uint Ah[4][4], Al[4][4];
    {
        const uint* whi = (const uint*)g_Whi;
        const uint* wlo = (const uint*)g_Wlo;
#pragma unroll
        for (int t = 0; t < 4; t++) {
            int r0 = g, r1 = g + 8;
            int c0 = t * 8 + mm, c1 = c0 + 4;
            Ah[t][0] = whi[r0 * 32 + c0];
            Ah[t][1] = whi[r1 * 32 + c0];
            Ah[t][2] = whi[r0 * 32 + c1];
            Ah[t][3] = whi[r1 * 32 + c1];
            Al[t][0] = wlo[r0 * 32 + c0];
            Al[t][1] = wlo[r1 * 32 + c0];
            Al[t][2] = wlo[r0 * 32 + c1];
            Al[t][3] = wlo[r1 * 32 + c1];
        }
    }

    // Walsh signs for states g / g+8 (shared bits 2..0)
    float s4 = (lane & 16) ? -1.f : 1.f;
    float s2 = (lane & 8)  ? -1.f : 1.f;
    float s1 = (lane & 4)  ? -1.f : 1.f;

    float4* out4 = reinterpret_cast<float4*>(out);

#pragma unroll 1
    for (int it = 0; it < TITER; it++) {
        int Wi = (blockIdx.x * NWARP + wrp) * TITER + it;
        if (Wi >= WTOT) break;

        // ---- encode patch Wi*32 + lane ----
        {
            int idx = Wi * 32 + lane;
            int b  = idx / Pc;
            int p  = idx - b * Pc;
            int ph = p / PWc;
            int pw = p - ph * PWc;

            float  cth[NQ];
            float2 eph[NQ];
#pragma unroll
            for (int n = 0; n < NQ; n++) {
                int dy = n >> 1, dx = n & 1;
                const float* px = x + ((((b * Hc) + (ph + dy)) * Wc + (pw + dx)) * 3);
                float l1 = px[1];
                float l2 = px[2];
                float sb, cb, sp, cp;
                __sincosf(1.57079632679489662f * l1, &sb, &cb);
                __sincosf(3.14159265358979323f * l2, &sp, &cp);
                cth[n] = cb;
                eph[n] = make_float2(sb * cp, sb * sp);
            }
            float2 ab[4], cd[4];
            ab[0] = make_float2(cth[0] * cth[1], 0.f);
            ab[1] = make_float2(cth[0] * eph[1].x, cth[0] * eph[1].y);
            ab[2] = make_float2(eph[0].x * cth[1], eph[0].y * cth[1]);
            ab[3] = cmul(eph[0], eph[1]);
            cd[0] = make_float2(cth[2] * cth[3], 0.f);
            cd[1] = make_float2(cth[2] * eph[3].x, cth[2] * eph[3].y);
            cd[2] = make_float2(eph[2].x * cth[3], eph[2].y * cth[3]);
            cd[3] = cmul(eph[2], eph[3]);

            float2 psi[16];
#pragma unroll
            for (int i = 0; i < 4; i++)
#pragma unroll
                for (int j = 0; j < 4; j++)
                    psi[i * 4 + j] = cmul(ab[i], cd[j]);

            float4* vrow = reinterpret_cast<float4*>(&v_sm[wrp][lane][0]);
#pragma unroll
            for (int q = 0; q < 4; q++)
                vrow[q] = make_float4(psi[4*q].x, psi[4*q+1].x,
                                      psi[4*q+2].x, psi[4*q+3].x);
#pragma unroll
            for (int q = 0; q < 4; q++)
                vrow[4 + q] = make_float4(psi[4*q].y, psi[4*q+1].y,
                                          psi[4*q+2].y, psi[4*q+3].y);
        }
        __syncwarp();

        // ---- 4 n-tiles of 8 patches ----
#pragma unroll
        for (int nt = 0; nt < 4; nt++) {
            // B fragments for v (all 4 k-tiles up front; reused by d-pass)
            uint Bh[4][2], Bl[4][2];
            const float* vb = &v_sm[wrp][nt * 8 + g][0];
#pragma unroll
            for (int t = 0; t < 4; t++) {
                float f0 = vb[t * 8 + mm];
                float f1 = vb[t * 8 + mm + 4];
                uint bh0 = tf32cvt(f0);
                uint bh1 = tf32cvt(f1);
                Bh[t][0] = bh0;
                Bh[t][1] = bh1;
                Bl[t][0] = tf32cvt(f0 - __uint_as_float(bh0));
                Bl[t][1] = tf32cvt(f1 - __uint_as_float(bh1));
            }

            float c0 = 0.f, c1 = 0.f, c2 = 0.f, c3 = 0.f;   // amp_re
            float d0 = 0.f, d1 = 0.f, d2 = 0.f, d3 = 0.f;   // amp_im
#pragma unroll
            for (int t = 0; t < 4; t++) {
                MMA_TF32(c0, c1, c2, c3,
                         Ah[t][0], Ah[t][1], Ah[t][2], Ah[t][3],
                         Bh[t][0], Bh[t][1]);
                MMA_TF32(c0, c1, c2, c3,
                         Ah[t][0], Ah[t][1], Ah[t][2], Ah[t][3],
                         Bl[t][0], Bl[t][1]);
                MMA_TF32(c0, c1, c2, c3,
                         Al[t][0], Al[t][1], Al[t][2], Al[t][3],
                         Bh[t][0], Bh[t][1]);
            }
            // d-pass: B'(t) = B((t+2)&3), negated for t>=2 (sign-bit XOR)
#pragma unroll
            for (int t = 0; t < 4; t++) {
                int  src = (t + 2) & 3;
                uint sx  = (t >= 2) ? 0x80000000u : 0u;
                uint bh0 = Bh[src][0] ^ sx, bh1 = Bh[src][1] ^ sx;
                uint bl0 = Bl[src][0] ^ sx, bl1 = Bl[src][1] ^ sx;
                MMA_TF32(d0, d1, d2, d3,
                         Ah[t][0], Ah[t][1], Ah[t][2], Ah[t][3],
                         bh0, bh1);
                MMA_TF32(d0, d1, d2, d3,
                         Ah[t][0], Ah[t][1], Ah[t][2], Ah[t][3],
                         bl0, bl1);
                MMA_TF32(d0, d1, d2, d3,
                         Al[t][0], Al[t][1], Al[t][2], Al[t][3],
                         bh0, bh1);
            }

            // ---- epilogue ----
            float pa0 = fmaf(c0, c0, d0 * d0);   // state g,   col 2mm
            float pb0 = fmaf(c2, c2, d2 * d2);   // state g+8, col 2mm
            float pa1 = fmaf(c1, c1, d1 * d1);   // state g,   col 2mm+1
            float pb1 = fmaf(c3, c3, d3 * d3);   // state g+8, col 2mm+1

            float sum0 = pa0 + pb0, sum1 = pa1 + pb1;
            float z0_0 = pa0 - pb0,  z0_1 = pa1 - pb1;
            float z1_0 = s4 * sum0,  z1_1 = s4 * sum1;
            float z2_0 = s2 * sum0,  z2_1 = s2 * sum1;
            float z3_0 = s1 * sum0,  z3_1 = s1 * sum1;

#pragma unroll
            for (int mask = 4; mask <= 16; mask <<= 1) {
                z0_0 += __shfl_xor_sync(0xffffffffu, z0_0, mask);
                z1_0 += __shfl_xor_sync(0xffffffffu, z1_0, mask);
                z2_0 += __shfl_xor_sync(0xffffffffu, z2_0, mask);
                z3_0 += __shfl_xor_sync(0xffffffffu, z3_0, mask);
                z0_1 += __shfl_xor_sync(0xffffffffu, z0_1, mask);
                z1_1 += __shfl_xor_sync(0xffffffffu, z1_1, mask);
                z2_1 += __shfl_xor_sync(0xffffffffu, z2_1, mask);
                z3_1 += __shfl_xor_sync(0xffffffffu, z3_1, mask);
            }

            if (g == 0) {
                int pbase = Wi * 32 + nt * 8 + 2 * mm;
                out4[pbase]     = make_float4(z0_0, z1_0, z2_0, z3_0);
                out4[pbase + 1] = make_float4(z0_1, z1_1, z2_1, z3_1);
            }
        }
        __syncwarp();
    }
}

extern "C" void kernel_launch(void* const* d_in, const int* in_sizes, int n_in,
                              void* d_out, int out_size) {
    const float* x = (const float*)d_in[0];
    const float* w = (const float*)d_in[1];
    float* out = (float*)d_out;

    k_build_U<<<1, 256>>>(w);
    k_qcnn<<<NBLK, NWARP * 32>>>(x, out);
}

// round 10
// speedup vs baseline: 1.1427x; 1.0027x over previous
#include <cuda_runtime.h>
#include <cstdint>

// QCNN_58025008169535
// x: [32,128,128,3] f32, w: [4,4,3] f32 -> out: [32, 127*127, 4] f32
//
// Tensor-core formulation. amp_re = A0 v, amp_im = A0 v', where
// A0 = [ReU | -ImU] (16x32), v = [Re psi; Im psi], v' = [Im psi; -Re psi].
// v' B-fragments are v's fragments with k-tiles rotated by 2 and sign-
// flipped for the rotated-in Re half. 3-pass tf32 hi/lo split.
// R10: interleaved c/d mma chains + WHT butterfly epilogue.

#define DIM 16
#define NL 4
#define NQ 4

static constexpr int Bc = 32, Hc = 128, Wc = 128;
static constexpr int PHc = Hc - 1, PWc = Wc - 1;
static constexpr int Pc = PHc * PWc;          // 16129
static constexpr int TOTALc = Bc * Pc;        // 516128
static constexpr int WTOT = TOTALc / 32;      // 16129 warp-iterations
static constexpr int TITER = 2;               // warp-iters per warp
static constexpr int NWARP = 4;               // warps per block
static constexpr int NBLK = (WTOT + NWARP * TITER - 1) / (NWARP * TITER);  // 2017

typedef unsigned int uint;

// W split: Whi = tf32(W), Wlo = tf32(W - Whi). Row-major 32x32 (top 16 rows used).
__device__ float g_Whi[32 * 32];
__device__ float g_Wlo[32 * 32];

__device__ __forceinline__ float2 cmul(float2 a, float2 b) {
    return make_float2(fmaf(a.x, b.x, -a.y * b.y), fmaf(a.x, b.y, a.y * b.x));
}
__device__ __forceinline__ float2 cadd(float2 a, float2 b) {
    return make_float2(a.x + b.x, a.y + b.y);
}
__device__ __forceinline__ uint tf32cvt(float f) {
    uint r; asm("cvt.rna.tf32.f32 %0, %1;" : "=r"(r) : "f"(f)); return r;
}

#define MMA_TF32(C0, C1, C2, C3, A0, A1, A2, A3, B0, B1)                      \
    asm volatile(                                                             \
        "mma.sync.aligned.m16n8k8.row.col.f32.tf32.tf32.f32 "                 \
        "{%0,%1,%2,%3}, {%4,%5,%6,%7}, {%8,%9}, {%0,%1,%2,%3};"               \
        : "+f"(C0), "+f"(C1), "+f"(C2), "+f"(C3)                              \
        : "r"(A0), "r"(A1), "r"(A2), "r"(A3), "r"(B0), "r"(B1))

// ---------------------------------------------------------------------------
// Kernel 1 (256 threads): build U, emit W as tf32 hi/lo split.
// ---------------------------------------------------------------------------
__global__ void k_build_U(const float* __restrict__ w) {
    __shared__ float2 sg[16][4];
    __shared__ float2 sM[4][DIM][DIM];
    __shared__ float2 sT[2][DIM][DIM];

    int tid = threadIdx.x;

    if (tid < 16) {
        float wx = w[tid * 3 + 0];
        float wy = w[tid * 3 + 1];
        float wz = w[tid * 3 + 2];
        float cx, sx, cy, sy, cz, sz;
        sincosf(0.5f * wx, &sx, &cx);
        sincosf(0.5f * wy, &sy, &cy);
        sincosf(0.5f * wz, &sz, &cz);
        float2 m00 = make_float2(cy * cx,  sy * sx);
        float2 m01 = make_float2(-sy * cx, -cy * sx);
        float2 m10 = make_float2(sy * cx,  -cy * sx);
        float2 m11 = make_float2(cy * cx,  -sy * sx);
        float2 e0 = make_float2(cz, -sz);
        float2 e1 = make_float2(cz,  sz);
        sg[tid][0] = cmul(e0, m00);
        sg[tid][1] = cmul(e0, m01);
        sg[tid][2] = cmul(e1, m10);
        sg[tid][3] = cmul(e1, m11);
    }
    __syncthreads();

#pragma unroll
    for (int r = 0; r < 4; r++) {
        int e = tid + 256 * r;
        int h = e >> 8;
        int st = e & 255;
        int s = st >> 4, t = st & 15;
        float2 prod = make_float2(1.f, 0.f);
#pragma unroll
        for (int q = 0; q < NQ; q++) {
            int sb = (s >> (3 - q)) & 1;
            int tb = (t >> (3 - q)) & 1;
            prod = cmul(prod, sg[h * 4 + q][sb * 2 + tb]);
        }
        bool neg = (((s & 12) == 12) ^ ((s & 3) == 3)) ^ ((s & 6) == 6);
        if (neg) { prod.x = -prod.x; prod.y = -prod.y; }
        sM[h][s][t] = prod;
    }
    __syncthreads();

    {
        int s = tid >> 4, t = tid & 15;
        float2 a1 = make_float2(0.f, 0.f);
        float2 a2 = make_float2(0.f, 0.f);
#pragma unroll
        for (int k = 0; k < DIM; k++) {
            a1 = cadd(a1, cmul(sM[1][s][k], sM[0][k][t]));
            a2 = cadd(a2, cmul(sM[3][s][k], sM[2][k][t]));
        }
        sT[0][s][t] = a1;
        sT[1][s][t] = a2;
    }
    __syncthreads();

    {
        int s = tid >> 4, t = tid & 15;
        float2 u = make_float2(0.f, 0.f);
#pragma unroll
        for (int k = 0; k < DIM; k++)
            u = cadd(u, cmul(sT[1][s][k], sT[0][k][t]));

        // W = [[Re, -Im],[Im, Re]], hi/lo split (bottom half unused but kept)
        float vals[4] = {u.x, -u.y, u.y, u.x};
        int   idxs[4] = {s * 32 + t, s * 32 + 16 + t,
                         (16 + s) * 32 + t, (16 + s) * 32 + 16 + t};
#pragma unroll
        for (int q = 0; q < 4; q++) {
            float f  = vals[q];
            uint  hb = tf32cvt(f);
            float hf = __uint_as_float(hb);
            uint  lb = tf32cvt(f - hf);
            g_Whi[idxs[q]] = hf;
            g_Wlo[idxs[q]] = __uint_as_float(lb);
        }
    }
}

// ---------------------------------------------------------------------------
// Kernel 2: tensor-core batched matvec, interleaved chains + WHT epilogue.
// ---------------------------------------------------------------------------
__global__ void __launch_bounds__(128)
k_qcnn(const float* __restrict__ x, float* __restrict__ out) {
    __shared__ float v_sm[NWARP][32][36];   // [warp][patch][k], pad 36

    int tid  = threadIdx.x;
    int wrp  = tid >> 5;
    int lane = tid & 31;
    int g    = lane >> 2;     // fragment row group (0..7)
    int mm   = lane & 3;      // fragment col-in-group

    // --- A fragments: top 16 rows of Whi/Wlo, 4 K-tiles x 4 regs ---
    uint Ah[4][4], Al[4][4];
    {
        const uint* whi = (const uint*)g_Whi;
        const uint* wlo = (const uint*)g_Wlo;
#pragma unroll
        for (int t = 0; t < 4; t++) {
            int r0 = g, r1 = g + 8;
            int c0 = t * 8 + mm, c1 = c0 + 4;
            Ah[t][0] = whi[r0 * 32 + c0];
            Ah[t][1] = whi[r1 * 32 + c0];
            Ah[t][2] = whi[r0 * 32 + c1];
            Ah[t][3] = whi[r1 * 32 + c1];
            Al[t][0] = wlo[r0 * 32 + c0];
            Al[t][1] = wlo[r1 * 32 + c0];
            Al[t][2] = wlo[r0 * 32 + c1];
            Al[t][3] = wlo[r1 * 32 + c1];
        }
    }

    // WHT destination role for this lane's g:
    //   g==0 -> z0 (from w), g==4 -> z1 (from u), g==2 -> z2, g==1 -> z3
    int comp = -1;
    if (g == 0) comp = 0;
    else if (g == 4) comp = 1;
    else if (g == 2) comp = 2;
    else if (g == 1) comp = 3;

#pragma unroll 1
    for (int it = 0; it < TITER; it++) {
        int Wi = (blockIdx.x * NWARP + wrp) * TITER + it;
        if (Wi >= WTOT) break;

        // ---- encode patch Wi*32 + lane ----
        {
            int idx = Wi * 32 + lane;
            int b  = idx / Pc;
            int p  = idx - b * Pc;
            int ph = p / PWc;
            int pw = p - ph * PWc;

            float  cth[NQ];
            float2 eph[NQ];
#pragma unroll
            for (int n = 0; n < NQ; n++) {
                int dy = n >> 1, dx = n & 1;
                const float* px = x + ((((b * Hc) + (ph + dy)) * Wc + (pw + dx)) * 3);
                float l1 = px[1];
                float l2 = px[2];
                float sb, cb, sp, cp;
                __sincosf(1.57079632679489662f * l1, &sb, &cb);
                __sincosf(3.14159265358979323f * l2, &sp, &cp);
                cth[n] = cb;
                eph[n] = make_float2(sb * cp, sb * sp);
            }
            float2 ab[4], cd[4];
            ab[0] = make_float2(cth[0] * cth[1], 0.f);
            ab[1] = make_float2(cth[0] * eph[1].x, cth[0] * eph[1].y);
            ab[2] = make_float2(eph[0].x * cth[1], eph[0].y * cth[1]);
            ab[3] = cmul(eph[0], eph[1]);
            cd[0] = make_float2(cth[2] * cth[3], 0.f);
            cd[1] = make_float2(cth[2] * eph[3].x, cth[2] * eph[3].y);
            cd[2] = make_float2(eph[2].x * cth[3], eph[2].y * cth[3]);
            cd[3] = cmul(eph[2], eph[3]);

            float2 psi[16];
#pragma unroll
            for (int i = 0; i < 4; i++)
#pragma unroll
                for (int j = 0; j < 4; j++)
                    psi[i * 4 + j] = cmul(ab[i], cd[j]);

            float4* vrow = reinterpret_cast<float4*>(&v_sm[wrp][lane][0]);
#pragma unroll
            for (int q = 0; q < 4; q++)
                vrow[q] = make_float4(psi[4*q].x, psi[4*q+1].x,
                                      psi[4*q+2].x, psi[4*q+3].x);
#pragma unroll
            for (int q = 0; q < 4; q++)
                vrow[4 + q] = make_float4(psi[4*q].y, psi[4*q+1].y,
                                          psi[4*q+2].y, psi[4*q+3].y);
        }
        __syncwarp();

        // ---- 4 n-tiles of 8 patches ----
#pragma unroll
        for (int nt = 0; nt < 4; nt++) {
            // B fragments for v (k-tiles up front; d-pass reuses via rot+sign)
            uint Bh[4][2], Bl[4][2];
            const float* vb = &v_sm[wrp][nt * 8 + g][0];
#pragma unroll
            for (int t = 0; t < 4; t++) {
                float f0 = vb[t * 8 + mm];
                float f1 = vb[t * 8 + mm + 4];
                uint bh0 = tf32cvt(f0);
                uint bh1 = tf32cvt(f1);
                Bh[t][0] = bh0;
                Bh[t][1] = bh1;
                Bl[t][0] = tf32cvt(f0 - __uint_as_float(bh0));
                Bl[t][1] = tf32cvt(f1 - __uint_as_float(bh1));
            }

            float c0 = 0.f, c1 = 0.f, c2 = 0.f, c3 = 0.f;   // amp_re
            float d0 = 0.f, d1 = 0.f, d2 = 0.f, d3 = 0.f;   // amp_im
            // interleaved independent c/d chains
#pragma unroll
            for (int t = 0; t < 4; t++) {
                int  src = (t + 2) & 3;
                uint sx  = (t >= 2) ? 0x80000000u : 0u;
                uint ph0 = Bh[src][0] ^ sx, ph1 = Bh[src][1] ^ sx;
                uint pl0 = Bl[src][0] ^ sx, pl1 = Bl[src][1] ^ sx;
                MMA_TF32(c0, c1, c2, c3,
                         Ah[t][0], Ah[t][1], Ah[t][2], Ah[t][3],
                         Bh[t][0], Bh[t][1]);
                MMA_TF32(d0, d1, d2, d3,
                         Ah[t][0], Ah[t][1], Ah[t][2], Ah[t][3],
                         ph0, ph1);
                MMA_TF32(c0, c1, c2, c3,
                         Ah[t][0], Ah[t][1], Ah[t][2], Ah[t][3],
                         Bl[t][0], Bl[t][1]);
                MMA_TF32(d0, d1, d2, d3,
                         Ah[t][0], Ah[t][1], Ah[t][2], Ah[t][3],
                         pl0, pl1);
                MMA_TF32(c0, c1, c2, c3,
                         Al[t][0], Al[t][1], Al[t][2], Al[t][3],
                         Bh[t][0], Bh[t][1]);
                MMA_TF32(d0, d1, d2, d3,
                         Al[t][0], Al[t][1], Al[t][2], Al[t][3],
                         ph0, ph1);
            }

            // ---- WHT epilogue ----
            float pa0 = fmaf(c0, c0, d0 * d0);   // state g,   col 2mm
            float pb0 = fmaf(c2, c2, d2 * d2);   // state g+8, col 2mm
            float pa1 = fmaf(c1, c1, d1 * d1);   // state g,   col 2mm+1
            float pb1 = fmaf(c3, c3, d3 * d3);   // state g+8, col 2mm+1

            float u0 = pa0 + pb0, w0 = pa0 - pb0;
            float u1 = pa1 + pb1, w1 = pa1 - pb1;

            // 3-round butterfly over lane bits {4,8,16} (the g bits):
            // x' = partner + sg*x, sg = -1 if this lane has the bit set.
#pragma unroll
            for (int r = 0; r < 3; r++) {
                int m = 4 << r;
                float sg = (lane & m) ? -1.f : 1.f;
                float p;
                p = __shfl_xor_sync(0xffffffffu, u0, m); u0 = fmaf(sg, u0, p);
                p = __shfl_xor_sync(0xffffffffu, u1, m); u1 = fmaf(sg, u1, p);
                p = __shfl_xor_sync(0xffffffffu, w0, m); w0 = fmaf(sg, w0, p);
                p = __shfl_xor_sync(0xffffffffu, w1, m); w1 = fmaf(sg, w1, p);
            }

            // lane g==0 holds z0 in w; g==4 holds z1 in u; g==2 -> z2; g==1 -> z3
            if (comp >= 0) {
                float v0 = (comp == 0) ? w0 : u0;
                float v1 = (comp == 0) ? w1 : u1;
                int p0 = Wi * 32 + nt * 8 + 2 * mm;
                out[p0 * 4 + comp]       = v0;
                out[(p0 + 1) * 4 + comp] = v1;
            }
        }
        __syncwarp();
    }
}

extern "C" void kernel_launch(void* const* d_in, const int* in_sizes, int n_in,
                              void* d_out, int out_size) {
    const float* x = (const float*)d_in[0];
    const float* w = (const float*)d_in[1];
    float* out = (float*)d_out;

    k_build_U<<<1, 256>>>(w);
    k_qcnn<<<NBLK, NWARP * 32>>>(x, out);
}

// round 11
// speedup vs baseline: 1.3330x; 1.1665x over previous
#include <cuda_runtime.h>
#include <cstdint>

// QCNN_58025008169535
// x: [32,128,128,3] f32, w: [4,4,3] f32 -> out: [32, 127*127, 4] f32
//
// Tensor-core formulation. amp_re = A0 v, amp_im = A0 v', where
// A0 = [ReU | -ImU] (16x32), v = [Re psi; Im psi], v' = [Im psi; -Re psi]
// (v' fragments = v fragments, k-tiles rotated by 2, sign-flipped t>=2).
// R11: 2-pass tf32 split (Ahi+Alo)*Btf32 — B converted once at encode and
// staged as tf32 bits; 16 mma/nt; regs capped for 8-block residency.

#define DIM 16
#define NL 4
#define NQ 4

static constexpr int Bc = 32, Hc = 128, Wc = 128;
static constexpr int PHc = Hc - 1, PWc = Wc - 1;
static constexpr int Pc = PHc * PWc;          // 16129
static constexpr int TOTALc = Bc * Pc;        // 516128
static constexpr int WTOT = TOTALc / 32;      // 16129 warp-iterations
static constexpr int TITER = 2;               // warp-iters per warp
static constexpr int NWARP = 4;               // warps per block
static constexpr int NBLK = (WTOT + NWARP * TITER - 1) / (NWARP * TITER);  // 2017

typedef unsigned int uint;

// W split: Whi = tf32(W), Wlo = tf32(W - Whi). Row-major 32x32 (top 16 rows used).
__device__ float g_Whi[32 * 32];
__device__ float g_Wlo[32 * 32];

__device__ __forceinline__ float2 cmul(float2 a, float2 b) {
    return make_float2(fmaf(a.x, b.x, -a.y * b.y), fmaf(a.x, b.y, a.y * b.x));
}
__device__ __forceinline__ float2 cadd(float2 a, float2 b) {
    return make_float2(a.x + b.x, a.y + b.y);
}
__device__ __forceinline__ uint tf32cvt(float f) {
    uint r; asm("cvt.rna.tf32.f32 %0, %1;" : "=r"(r) : "f"(f)); return r;
}

#define MMA_TF32(C0, C1, C2, C3, A0, A1, A2, A3, B0, B1)                      \
    asm volatile(                                                             \
        "mma.sync.aligned.m16n8k8.row.col.f32.tf32.tf32.f32 "                 \
        "{%0,%1,%2,%3}, {%4,%5,%6,%7}, {%8,%9}, {%0,%1,%2,%3};"               \
        : "+f"(C0), "+f"(C1), "+f"(C2), "+f"(C3)                              \
        : "r"(A0), "r"(A1), "r"(A2), "r"(A3), "r"(B0), "r"(B1))

// ---------------------------------------------------------------------------
// Kernel 1 (256 threads): build U, emit W as tf32 hi/lo split.
// ---------------------------------------------------------------------------
__global__ void k_build_U(const float* __restrict__ w) {
    __shared__ float2 sg[16][4];
    __shared__ float2 sM[4][DIM][DIM];
    __shared__ float2 sT[2][DIM][DIM];

    int tid = threadIdx.x;

    if (tid < 16) {
        float wx = w[tid * 3 + 0];
        float wy = w[tid * 3 + 1];
        float wz = w[tid * 3 + 2];
        float cx, sx, cy, sy, cz, sz;
        sincosf(0.5f * wx, &sx, &cx);
        sincosf(0.5f * wy, &sy, &cy);
        sincosf(0.5f * wz, &sz, &cz);
        float2 m00 = make_float2(cy * cx,  sy * sx);
        float2 m01 = make_float2(-sy * cx, -cy * sx);
        float2 m10 = make_float2(sy * cx,  -cy * sx);
        float2 m11 = make_float2(cy * cx,  -sy * sx);
        float2 e0 = make_float2(cz, -sz);
        float2 e1 = make_float2(cz,  sz);
        sg[tid][0] = cmul(e0, m00);
        sg[tid][1] = cmul(e0, m01);
        sg[tid][2] = cmul(e1, m10);
        sg[tid][3] = cmul(e1, m11);
    }
    __syncthreads();

#pragma unroll
    for (int r = 0; r < 4; r++) {
        int e = tid + 256 * r;
        int h = e >> 8;
        int st = e & 255;
        int s = st >> 4, t = st & 15;
        float2 prod = make_float2(1.f, 0.f);
#pragma unroll
        for (int q = 0; q < NQ; q++) {
            int sb = (s >> (3 - q)) & 1;
            int tb = (t >> (3 - q)) & 1;
            prod = cmul(prod, sg[h * 4 + q][sb * 2 + tb]);
        }
        bool neg = (((s & 12) == 12) ^ ((s & 3) == 3)) ^ ((s & 6) == 6);
        if (neg) { prod.x = -prod.x; prod.y = -prod.y; }
        sM[h][s][t] = prod;
    }
    __syncthreads();

    {
        int s = tid >> 4, t = tid & 15;
        float2 a1 = make_float2(0.f, 0.f);
        float2 a2 = make_float2(0.f, 0.f);
#pragma unroll
        for (int k = 0; k < DIM; k++) {
            a1 = cadd(a1, cmul(sM[1][s][k], sM[0][k][t]));
            a2 = cadd(a2, cmul(sM[3][s][k], sM[2][k][t]));
        }
        sT[0][s][t] = a1;
        sT[1][s][t] = a2;
    }
    __syncthreads();

    {
        int s = tid >> 4, t = tid & 15;
        float2 u = make_float2(0.f, 0.f);
#pragma unroll
        for (int k = 0; k < DIM; k++)
            u = cadd(u, cmul(sT[1][s][k], sT[0][k][t]));

        // W = [[Re, -Im],[Im, Re]], hi/lo split (bottom half unused but kept)
        float vals[4] = {u.x, -u.y, u.y, u.x};
        int   idxs[4] = {s * 32 + t, s * 32 + 16 + t,
                         (16 + s) * 32 + t, (16 + s) * 32 + 16 + t};
#pragma unroll
        for (int q = 0; q < 4; q++) {
            float f  = vals[q];
            uint  hb = tf32cvt(f);
            float hf = __uint_as_float(hb);
            uint  lb = tf32cvt(f - hf);
            g_Whi[idxs[q]] = hf;
            g_Wlo[idxs[q]] = __uint_as_float(lb);
        }
    }
}

// ---------------------------------------------------------------------------
// Kernel 2: tensor-core batched matvec, 2-pass A split, B staged as tf32.
// ---------------------------------------------------------------------------
__global__ void __launch_bounds__(128, 8)
k_qcnn(const float* __restrict__ x, float* __restrict__ out) {
    __shared__ uint v_sm[NWARP][32][36];   // tf32 bits, [warp][patch][k], pad 36

    int tid  = threadIdx.x;
    int wrp  = tid >> 5;
    int lane = tid & 31;
    int g    = lane >> 2;     // fragment row group (0..7)
    int mm   = lane & 3;      // fragment col-in-group

    // --- A fragments: top 16 rows of Whi/Wlo, 4 K-tiles x 4 regs each ---
    uint Ah[4][4], Al[4][4];
    {
        const uint* whi = (const uint*)g_Whi;
        const uint* wlo = (const uint*)g_Wlo;
#pragma unroll
        for (int t = 0; t < 4; t++) {
            int r0 = g, r1 = g + 8;
            int c0 = t * 8 + mm, c1 = c0 + 4;
            Ah[t][0] = whi[r0 * 32 + c0];
            Ah[t][1] = whi[r1 * 32 + c0];
            Ah[t][2] = whi[r0 * 32 + c1];
            Ah[t][3] = whi[r1 * 32 + c1];
            Al[t][0] = wlo[r0 * 32 + c0];
            Al[t][1] = wlo[r1 * 32 + c0];
            Al[t][2] = wlo[r0 * 32 + c1];
            Al[t][3] = wlo[r1 * 32 + c1];
        }
    }

    // WHT destination role: g==0 -> z0 (from w), g==4 -> z1, g==2 -> z2, g==1 -> z3
    int comp = -1;
    if (g == 0) comp = 0;
    else if (g == 4) comp = 1;
    else if (g == 2) comp = 2;
    else if (g == 1) comp = 3;

#pragma unroll 1
    for (int it = 0; it < TITER; it++) {
        int Wi = (blockIdx.x * NWARP + wrp) * TITER + it;
        if (Wi >= WTOT) break;

        // ---- encode patch Wi*32 + lane, stage psi as tf32 bits ----
        {
            int idx = Wi * 32 + lane;
            int b  = idx / Pc;
            int p  = idx - b * Pc;
            int ph = p / PWc;
            int pw = p - ph * PWc;

            float  cth[NQ];
            float2 eph[NQ];
#pragma unroll
            for (int n = 0; n < NQ; n++) {
                int dy = n >> 1, dx = n & 1;
                const float* px = x + ((((b * Hc) + (ph + dy)) * Wc + (pw + dx)) * 3);
                float l1 = px[1];
                float l2 = px[2];
                float sb, cb, sp, cp;
                __sincosf(1.57079632679489662f * l1, &sb, &cb);
                __sincosf(3.14159265358979323f * l2, &sp, &cp);
                cth[n] = cb;
                eph[n] = make_float2(sb * cp, sb * sp);
            }
            float2 ab[4], cd[4];
            ab[0] = make_float2(cth[0] * cth[1], 0.f);
            ab[1] = make_float2(cth[0] * eph[1].x, cth[0] * eph[1].y);
            ab[2] = make_float2(eph[0].x * cth[1], eph[0].y * cth[1]);
            ab[3] = cmul(eph[0], eph[1]);
            cd[0] = make_float2(cth[2] * cth[3], 0.f);
            cd[1] = make_float2(cth[2] * eph[3].x, cth[2] * eph[3].y);
            cd[2] = make_float2(eph[2].x * cth[3], eph[2].y * cth[3]);
            cd[3] = cmul(eph[2], eph[3]);

            float2 psi[16];
#pragma unroll
            for (int i = 0; i < 4; i++)
#pragma unroll
                for (int j = 0; j < 4; j++)
                    psi[i * 4 + j] = cmul(ab[i], cd[j]);

            uint4* vrow = reinterpret_cast<uint4*>(&v_sm[wrp][lane][0]);
#pragma unroll
            for (int q = 0; q < 4; q++)
                vrow[q] = make_uint4(tf32cvt(psi[4*q].x),   tf32cvt(psi[4*q+1].x),
                                     tf32cvt(psi[4*q+2].x), tf32cvt(psi[4*q+3].x));
#pragma unroll
            for (int q = 0; q < 4; q++)
                vrow[4 + q] = make_uint4(tf32cvt(psi[4*q].y),   tf32cvt(psi[4*q+1].y),
                                         tf32cvt(psi[4*q+2].y), tf32cvt(psi[4*q+3].y));
        }
        __syncwarp();

        // ---- 4 n-tiles of 8 patches ----
#pragma unroll
        for (int nt = 0; nt < 4; nt++) {
            // B fragments (tf32 bits, no conversion needed)
            uint Bh[4][2];
            const uint* vb = &v_sm[wrp][nt * 8 + g][0];
#pragma unroll
            for (int t = 0; t < 4; t++) {
                Bh[t][0] = vb[t * 8 + mm];
                Bh[t][1] = vb[t * 8 + mm + 4];
            }

            float c0 = 0.f, c1 = 0.f, c2 = 0.f, c3 = 0.f;   // amp_re
            float d0 = 0.f, d1 = 0.f, d2 = 0.f, d3 = 0.f;   // amp_im
#pragma unroll
            for (int t = 0; t < 4; t++) {
                int  src = (t + 2) & 3;
                uint sx  = (t >= 2) ? 0x80000000u : 0u;
                uint p0 = Bh[src][0] ^ sx, p1 = Bh[src][1] ^ sx;
                MMA_TF32(c0, c1, c2, c3,
                         Ah[t][0], Ah[t][1], Ah[t][2], Ah[t][3],
                         Bh[t][0], Bh[t][1]);
                MMA_TF32(d0, d1, d2, d3,
                         Ah[t][0], Ah[t][1], Ah[t][2], Ah[t][3],
                         p0, p1);
                MMA_TF32(c0, c1, c2, c3,
                         Al[t][0], Al[t][1], Al[t][2], Al[t][3],
                         Bh[t][0], Bh[t][1]);
                MMA_TF32(d0, d1, d2, d3,
                         Al[t][0], Al[t][1], Al[t][2], Al[t][3],
                         p0, p1);
            }

            // ---- WHT epilogue ----
            float pa0 = fmaf(c0, c0, d0 * d0);   // state g,   col 2mm
            float pb0 = fmaf(c2, c2, d2 * d2);   // state g+8, col 2mm
            float pa1 = fmaf(c1, c1, d1 * d1);   // state g,   col 2mm+1
            float pb1 = fmaf(c3, c3, d3 * d3);   // state g+8, col 2mm+1

            float u0 = pa0 + pb0, w0 = pa0 - pb0;
            float u1 = pa1 + pb1, w1 = pa1 - pb1;

#pragma unroll
            for (int r = 0; r < 3; r++) {
                int m = 4 << r;
                float sg = (lane & m) ? -1.f : 1.f;
                float p;
                p = __shfl_xor_sync(0xffffffffu, u0, m); u0 = fmaf(sg, u0, p);
                p = __shfl_xor_sync(0xffffffffu, u1, m); u1 = fmaf(sg, u1, p);
                p = __shfl_xor_sync(0xffffffffu, w0, m); w0 = fmaf(sg, w0, p);
                p = __shfl_xor_sync(0xffffffffu, w1, m); w1 = fmaf(sg, w1, p);
            }

            if (comp >= 0) {
                float v0 = (comp == 0) ? w0 : u0;
                float v1 = (comp == 0) ? w1 : u1;
                int p0 = Wi * 32 + nt * 8 + 2 * mm;
                out[p0 * 4 + comp]       = v0;
                out[(p0 + 1) * 4 + comp] = v1;
            }
        }
        __syncwarp();
    }
}

extern "C" void kernel_launch(void* const* d_in, const int* in_sizes, int n_in,
                              void* d_out, int out_size) {
    const float* x = (const float*)d_in[0];
    const float* w = (const float*)d_in[1];
    float* out = (float*)d_out;

    k_build_U<<<1, 256>>>(w);
    k_qcnn<<<NBLK, NWARP * 32>>>(x, out);
}

// round 12
// speedup vs baseline: 1.3570x; 1.0180x over previous
#include <cuda_runtime.h>
#include <cstdint>

// QCNN_58025008169535
// x: [32,128,128,3] f32, w: [4,4,3] f32 -> out: [32, 127*127, 4] f32
//
// Tensor-core formulation. amp_re = A0 v, amp_im = A0 v', where
// A0 = [ReU | -ImU] (16x32), v = [Re psi; Im psi], v' = [Im psi; -Re psi]
// (v' fragments = v fragments, k-tiles rotated by 2, sign-flipped t>=2).
// 2-pass tf32 split (Ahi+Alo)*Btf32; B staged as tf32 bits at encode.
// R12: 2-deep software pipeline over nt-tiles (two accumulator sets) so each
// epilogue's mma-wait + shfl chain hides under the next tile's mma burst.

#define DIM 16
#define NL 4
#define NQ 4

static constexpr int Bc = 32, Hc = 128, Wc = 128;
static constexpr int PHc = Hc - 1, PWc = Wc - 1;
static constexpr int Pc = PHc * PWc;          // 16129
static constexpr int TOTALc = Bc * Pc;        // 516128
static constexpr int WTOT = TOTALc / 32;      // 16129 warp-iterations
static constexpr int TITER = 2;               // warp-iters per warp
static constexpr int NWARP = 4;               // warps per block
static constexpr int NBLK = (WTOT + NWARP * TITER - 1) / (NWARP * TITER);  // 2017

typedef unsigned int uint;

// W split: Whi = tf32(W), Wlo = tf32(W - Whi). Row-major 32x32 (top 16 rows used).
__device__ float g_Whi[32 * 32];
__device__ float g_Wlo[32 * 32];

__device__ __forceinline__ float2 cmul(float2 a, float2 b) {
    return make_float2(fmaf(a.x, b.x, -a.y * b.y), fmaf(a.x, b.y, a.y * b.x));
}
__device__ __forceinline__ float2 cadd(float2 a, float2 b) {
    return make_float2(a.x + b.x, a.y + b.y);
}
__device__ __forceinline__ uint tf32cvt(float f) {
    uint r; asm("cvt.rna.tf32.f32 %0, %1;" : "=r"(r) : "f"(f)); return r;
}

#define MMA_TF32(C0, C1, C2, C3, A0, A1, A2, A3, B0, B1)                      \
    asm volatile(                                                             \
        "mma.sync.aligned.m16n8k8.row.col.f32.tf32.tf32.f32 "                 \
        "{%0,%1,%2,%3}, {%4,%5,%6,%7}, {%8,%9}, {%0,%1,%2,%3};"               \
        : "+f"(C0), "+f"(C1), "+f"(C2), "+f"(C3)                              \
        : "r"(A0), "r"(A1), "r"(A2), "r"(A3), "r"(B0), "r"(B1))

// ---------------------------------------------------------------------------
// Kernel 1 (256 threads): build U, emit W as tf32 hi/lo split.
// ---------------------------------------------------------------------------
__global__ void k_build_U(const float* __restrict__ w) {
    __shared__ float2 sg[16][4];
    __shared__ float2 sM[4][DIM][DIM];
    __shared__ float2 sT[2][DIM][DIM];

    int tid = threadIdx.x;

    if (tid < 16) {
        float wx = w[tid * 3 + 0];
        float wy = w[tid * 3 + 1];
        float wz = w[tid * 3 + 2];
        float cx, sx, cy, sy, cz, sz;
        sincosf(0.5f * wx, &sx, &cx);
        sincosf(0.5f * wy, &sy, &cy);
        sincosf(0.5f * wz, &sz, &cz);
        float2 m00 = make_float2(cy * cx,  sy * sx);
        float2 m01 = make_float2(-sy * cx, -cy * sx);
        float2 m10 = make_float2(sy * cx,  -cy * sx);
        float2 m11 = make_float2(cy * cx,  -sy * sx);
        float2 e0 = make_float2(cz, -sz);
        float2 e1 = make_float2(cz,  sz);
        sg[tid][0] = cmul(e0, m00);
        sg[tid][1] = cmul(e0, m01);
        sg[tid][2] = cmul(e1, m10);
        sg[tid][3] = cmul(e1, m11);
    }
    __syncthreads();

#pragma unroll
    for (int r = 0; r < 4; r++) {
        int e = tid + 256 * r;
        int h = e >> 8;
        int st = e & 255;
        int s = st >> 4, t = st & 15;
        float2 prod = make_float2(1.f, 0.f);
#pragma unroll
        for (int q = 0; q < NQ; q++) {
            int sb = (s >> (3 - q)) & 1;
            int tb = (t >> (3 - q)) & 1;
            prod = cmul(prod, sg[h * 4 + q][sb * 2 + tb]);
        }
        bool neg = (((s & 12) == 12) ^ ((s & 3) == 3)) ^ ((s & 6) == 6);
        if (neg) { prod.x = -prod.x; prod.y = -prod.y; }
        sM[h][s][t] = prod;
    }
    __syncthreads();

    {
        int s = tid >> 4, t = tid & 15;
        float2 a1 = make_float2(0.f, 0.f);
        float2 a2 = make_float2(0.f, 0.f);
#pragma unroll
        for (int k = 0; k < DIM; k++) {
            a1 = cadd(a1, cmul(sM[1][s][k], sM[0][k][t]));
            a2 = cadd(a2, cmul(sM[3][s][k], sM[2][k][t]));
        }
        sT[0][s][t] = a1;
        sT[1][s][t] = a2;
    }
    __syncthreads();

    {
        int s = tid >> 4, t = tid & 15;
        float2 u = make_float2(0.f, 0.f);
#pragma unroll
        for (int k = 0; k < DIM; k++)
            u = cadd(u, cmul(sT[1][s][k], sT[0][k][t]));

        // W = [[Re, -Im],[Im, Re]], hi/lo split (bottom half unused but kept)
        float vals[4] = {u.x, -u.y, u.y, u.x};
        int   idxs[4] = {s * 32 + t, s * 32 + 16 + t,
                         (16 + s) * 32 + t, (16 + s) * 32 + 16 + t};
#pragma unroll
        for (int q = 0; q < 4; q++) {
            float f  = vals[q];
            uint  hb = tf32cvt(f);
            float hf = __uint_as_float(hb);
            uint  lb = tf32cvt(f - hf);
            g_Whi[idxs[q]] = hf;
            g_Wlo[idxs[q]] = __uint_as_float(lb);
        }
    }
}

// ---------------------------------------------------------------------------
// Kernel 2: tensor-core batched matvec, pipelined nt-tiles.
// ---------------------------------------------------------------------------
struct Acc { float c0, c1, c2, c3, d0, d1, d2, d3; };

__global__ void __launch_bounds__(128, 7)
k_qcnn(const float* __restrict__ x, float* __restrict__ out) {
    __shared__ uint v_sm[NWARP][32][36];   // tf32 bits, [warp][patch][k], pad 36

    int tid  = threadIdx.x;
    int wrp  = tid >> 5;
    int lane = tid & 31;
    int g    = lane >> 2;     // fragment row group (0..7)
    int mm   = lane & 3;      // fragment col-in-group

    // --- A fragments: top 16 rows of Whi/Wlo, 4 K-tiles x 4 regs each ---
    uint Ah[4][4], Al[4][4];
    {
        const uint* whi = (const uint*)g_Whi;
        const uint* wlo = (const uint*)g_Wlo;
#pragma unroll
        for (int t = 0; t < 4; t++) {
            int r0 = g, r1 = g + 8;
            int c0 = t * 8 + mm, c1 = c0 + 4;
            Ah[t][0] = whi[r0 * 32 + c0];
            Ah[t][1] = whi[r1 * 32 + c0];
            Ah[t][2] = whi[r0 * 32 + c1];
            Ah[t][3] = whi[r1 * 32 + c1];
            Al[t][0] = wlo[r0 * 32 + c0];
            Al[t][1] = wlo[r1 * 32 + c0];
            Al[t][2] = wlo[r0 * 32 + c1];
            Al[t][3] = wlo[r1 * 32 + c1];
        }
    }

    // WHT destination role: g==0 -> z0 (from w), g==4 -> z1, g==2 -> z2, g==1 -> z3
    int comp = -1;
    if (g == 0) comp = 0;
    else if (g == 4) comp = 1;
    else if (g == 2) comp = 2;
    else if (g == 1) comp = 3;

    // mma burst for one nt-tile -> fresh accumulators
    auto run_tile = [&](int nt, int Wi_unused, Acc& A) {
        uint Bh[4][2];
        const uint* vb = &v_sm[wrp][nt * 8 + g][0];
#pragma unroll
        for (int t = 0; t < 4; t++) {
            Bh[t][0] = vb[t * 8 + mm];
            Bh[t][1] = vb[t * 8 + mm + 4];
        }
        A.c0 = A.c1 = A.c2 = A.c3 = 0.f;
        A.d0 = A.d1 = A.d2 = A.d3 = 0.f;
#pragma unroll
        for (int t = 0; t < 4; t++) {
            int  src = (t + 2) & 3;
            uint sx  = (t >= 2) ? 0x80000000u : 0u;
            uint p0 = Bh[src][0] ^ sx, p1 = Bh[src][1] ^ sx;
            MMA_TF32(A.c0, A.c1, A.c2, A.c3,
                     Ah[t][0], Ah[t][1], Ah[t][2], Ah[t][3],
                     Bh[t][0], Bh[t][1]);
            MMA_TF32(A.d0, A.d1, A.d2, A.d3,
                     Ah[t][0], Ah[t][1], Ah[t][2], Ah[t][3],
                     p0, p1);
            MMA_TF32(A.c0, A.c1, A.c2, A.c3,
                     Al[t][0], Al[t][1], Al[t][2], Al[t][3],
                     Bh[t][0], Bh[t][1]);
            MMA_TF32(A.d0, A.d1, A.d2, A.d3,
                     Al[t][0], Al[t][1], Al[t][2], Al[t][3],
                     p0, p1);
        }
    };

    auto epilogue = [&](int nt, int Wi, const Acc& A) {
        float pa0 = fmaf(A.c0, A.c0, A.d0 * A.d0);   // state g,   col 2mm
        float pb0 = fmaf(A.c2, A.c2, A.d2 * A.d2);   // state g+8, col 2mm
        float pa1 = fmaf(A.c1, A.c1, A.d1 * A.d1);   // state g,   col 2mm+1
        float pb1 = fmaf(A.c3, A.c3, A.d3 * A.d3);   // state g+8, col 2mm+1

        float u0 = pa0 + pb0, w0 = pa0 - pb0;
        float u1 = pa1 + pb1, w1 = pa1 - pb1;

#pragma unroll
        for (int r = 0; r < 3; r++) {
            int m = 4 << r;
            float sg = (lane & m) ? -1.f : 1.f;
            float p;
            p = __shfl_xor_sync(0xffffffffu, u0, m); u0 = fmaf(sg, u0, p);
            p = __shfl_xor_sync(0xffffffffu, u1, m); u1 = fmaf(sg, u1, p);
            p = __shfl_xor_sync(0xffffffffu, w0, m); w0 = fmaf(sg, w0, p);
            p = __shfl_xor_sync(0xffffffffu, w1, m); w1 = fmaf(sg, w1, p);
        }

        if (comp >= 0) {
            float v0 = (comp == 0) ? w0 : u0;
            float v1 = (comp == 0) ? w1 : u1;
            int p0 = Wi * 32 + nt * 8 + 2 * mm;
            out[p0 * 4 + comp]       = v0;
            out[(p0 + 1) * 4 + comp] = v1;
        }
    };

#pragma unroll 1
    for (int it = 0; it < TITER; it++) {
        int Wi = (blockIdx.x * NWARP + wrp) * TITER + it;
        if (Wi >= WTOT) break;

        // ---- encode patch Wi*32 + lane, stage psi as tf32 bits ----
        {
            int idx = Wi * 32 + lane;
            int b  = idx / Pc;
            int p  = idx - b * Pc;
            int ph = p / PWc;
            int pw = p - ph * PWc;

            float  cth[NQ];
            float2 eph[NQ];
#pragma unroll
            for (int n = 0; n < NQ; n++) {
                int dy = n >> 1, dx = n & 1;
                const float* px = x + ((((b * Hc) + (ph + dy)) * Wc + (pw + dx)) * 3);
                float l1 = px[1];
                float l2 = px[2];
                float sb, cb, sp, cp;
                __sincosf(1.57079632679489662f * l1, &sb, &cb);
                __sincosf(3.14159265358979323f * l2, &sp, &cp);
                cth[n] = cb;
                eph[n] = make_float2(sb * cp, sb * sp);
            }
            float2 ab[4], cd[4];
            ab[0] = make_float2(cth[0] * cth[1], 0.f);
            ab[1] = make_float2(cth[0] * eph[1].x, cth[0] * eph[1].y);
            ab[2] = make_float2(eph[0].x * cth[1], eph[0].y * cth[1]);
            ab[3] = cmul(eph[0], eph[1]);
            cd[0] = make_float2(cth[2] * cth[3], 0.f);
            cd[1] = make_float2(cth[2] * eph[3].x, cth[2] * eph[3].y);
            cd[2] = make_float2(eph[2].x * cth[3], eph[2].y * cth[3]);
            cd[3] = cmul(eph[2], eph[3]);

            float2 psi[16];
#pragma unroll
            for (int i = 0; i < 4; i++)
#pragma unroll
                for (int j = 0; j < 4; j++)
                    psi[i * 4 + j] = cmul(ab[i], cd[j]);

            uint4* vrow = reinterpret_cast<uint4*>(&v_sm[wrp][lane][0]);
#pragma unroll
            for (int q = 0; q < 4; q++)
                vrow[q] = make_uint4(tf32cvt(psi[4*q].x),   tf32cvt(psi[4*q+1].x),
                                     tf32cvt(psi[4*q+2].x), tf32cvt(psi[4*q+3].x));
#pragma unroll
            for (int q = 0; q < 4; q++)
                vrow[4 + q] = make_uint4(tf32cvt(psi[4*q].y),   tf32cvt(psi[4*q+1].y),
                                         tf32cvt(psi[4*q+2].y), tf32cvt(psi[4*q+3].y));
        }
        __syncwarp();

        // ---- 2-deep pipelined nt-tiles: mma(n+1) issues before epi(n) ----
        Acc a0, a1;
        run_tile(0, Wi, a0);
        run_tile(1, Wi, a1);
        epilogue(0, Wi, a0);
        run_tile(2, Wi, a0);
        epilogue(1, Wi, a1);
        run_tile(3, Wi, a1);
        epilogue(2, Wi, a0);
        epilogue(3, Wi, a1);

        __syncwarp();
    }
}

extern "C" void kernel_launch(void* const* d_in, const int* in_sizes, int n_in,
                              void* d_out, int out_size) {
    const float* x = (const float*)d_in[0];
    const float* w = (const float*)d_in[1];
    float* out = (float*)d_out;

    k_build_U<<<1, 256>>>(w);
    k_qcnn<<<NBLK, NWARP * 32>>>(x, out);
}

// round 13
// speedup vs baseline: 1.3969x; 1.0294x over previous
#include <cuda_runtime.h>
#include <cstdint>

// QCNN_58025008169535
// x: [32,128,128,3] f32, w: [4,4,3] f32 -> out: [32, 127*127, 4] f32
//
// Tensor-core formulation. amp_re = A0 v, amp_im = A0 v', where
// A0 = [ReU | -ImU] (16x32), v = [Re psi; Im psi], v' = [Im psi; -Re psi]
// (v' fragments = v fragments, k-tiles rotated by 2, sign-flipped t>=2).
// 2-pass tf32 split (Ahi+Alo)*Btf32; B staged as tf32 bits at encode.
// R13: cross-iteration LDG prefetch (pixel loads for it+1 issue before the
// nt-loop of it) + TITER=4 single-wave grid.

#define DIM 16
#define NL 4
#define NQ 4

static constexpr int Bc = 32, Hc = 128, Wc = 128;
static constexpr int PHc = Hc - 1, PWc = Wc - 1;
static constexpr int Pc = PHc * PWc;          // 16129
static constexpr int TOTALc = Bc * Pc;        // 516128
static constexpr int WTOT = TOTALc / 32;      // 16129 warp-iterations
static constexpr int TITER = 4;               // warp-iters per warp
static constexpr int NWARP = 4;               // warps per block
static constexpr int NBLK = (WTOT + NWARP * TITER - 1) / (NWARP * TITER);  // 1009

typedef unsigned int uint;

// W split: Whi = tf32(W), Wlo = tf32(W - Whi). Row-major 32x32 (top 16 rows used).
__device__ float g_Whi[32 * 32];
__device__ float g_Wlo[32 * 32];

__device__ __forceinline__ float2 cmul(float2 a, float2 b) {
    return make_float2(fmaf(a.x, b.x, -a.y * b.y), fmaf(a.x, b.y, a.y * b.x));
}
__device__ __forceinline__ float2 cadd(float2 a, float2 b) {
    return make_float2(a.x + b.x, a.y + b.y);
}
__device__ __forceinline__ uint tf32cvt(float f) {
    uint r; asm("cvt.rna.tf32.f32 %0, %1;" : "=r"(r) : "f"(f)); return r;
}

#define MMA_TF32(C0, C1, C2, C3, A0, A1, A2, A3, B0, B1)                      \
    asm volatile(                                                             \
        "mma.sync.aligned.m16n8k8.row.col.f32.tf32.tf32.f32 "                 \
        "{%0,%1,%2,%3}, {%4,%5,%6,%7}, {%8,%9}, {%0,%1,%2,%3};"               \
        : "+f"(C0), "+f"(C1), "+f"(C2), "+f"(C3)                              \
        : "r"(A0), "r"(A1), "r"(A2), "r"(A3), "r"(B0), "r"(B1))

// ---------------------------------------------------------------------------
// Kernel 1 (256 threads): build U, emit W as tf32 hi/lo split.
// ---------------------------------------------------------------------------
__global__ void k_build_U(const float* __restrict__ w) {
    __shared__ float2 sg[16][4];
    __shared__ float2 sM[4][DIM][DIM];
    __shared__ float2 sT[2][DIM][DIM];

    int tid = threadIdx.x;

    if (tid < 16) {
        float wx = w[tid * 3 + 0];
        float wy = w[tid * 3 + 1];
        float wz = w[tid * 3 + 2];
        float cx, sx, cy, sy, cz, sz;
        sincosf(0.5f * wx, &sx, &cx);
        sincosf(0.5f * wy, &sy, &cy);
        sincosf(0.5f * wz, &sz, &cz);
        float2 m00 = make_float2(cy * cx,  sy * sx);
        float2 m01 = make_float2(-sy * cx, -cy * sx);
        float2 m10 = make_float2(sy * cx,  -cy * sx);
        float2 m11 = make_float2(cy * cx,  -sy * sx);
        float2 e0 = make_float2(cz, -sz);
        float2 e1 = make_float2(cz,  sz);
        sg[tid][0] = cmul(e0, m00);
        sg[tid][1] = cmul(e0, m01);
        sg[tid][2] = cmul(e1, m10);
        sg[tid][3] = cmul(e1, m11);
    }
    __syncthreads();

#pragma unroll
    for (int r = 0; r < 4; r++) {
        int e = tid + 256 * r;
        int h = e >> 8;
        int st = e & 255;
        int s = st >> 4, t = st & 15;
        float2 prod = make_float2(1.f, 0.f);
#pragma unroll
        for (int q = 0; q < NQ; q++) {
            int sb = (s >> (3 - q)) & 1;
            int tb = (t >> (3 - q)) & 1;
            prod = cmul(prod, sg[h * 4 + q][sb * 2 + tb]);
        }
        bool neg = (((s & 12) == 12) ^ ((s & 3) == 3)) ^ ((s & 6) == 6);
        if (neg) { prod.x = -prod.x; prod.y = -prod.y; }
        sM[h][s][t] = prod;
    }
    __syncthreads();

    {
        int s = tid >> 4, t = tid & 15;
        float2 a1 = make_float2(0.f, 0.f);
        float2 a2 = make_float2(0.f, 0.f);
#pragma unroll
        for (int k = 0; k < DIM; k++) {
            a1 = cadd(a1, cmul(sM[1][s][k], sM[0][k][t]));
            a2 = cadd(a2, cmul(sM[3][s][k], sM[2][k][t]));
        }
        sT[0][s][t] = a1;
        sT[1][s][t] = a2;
    }
    __syncthreads();

    {
        int s = tid >> 4, t = tid & 15;
        float2 u = make_float2(0.f, 0.f);
#pragma unroll
        for (int k = 0; k < DIM; k++)
            u = cadd(u, cmul(sT[1][s][k], sT[0][k][t]));

        float vals[4] = {u.x, -u.y, u.y, u.x};
        int   idxs[4] = {s * 32 + t, s * 32 + 16 + t,
                         (16 + s) * 32 + t, (16 + s) * 32 + 16 + t};
#pragma unroll
        for (int q = 0; q < 4; q++) {
            float f  = vals[q];
            uint  hb = tf32cvt(f);
            float hf = __uint_as_float(hb);
            uint  lb = tf32cvt(f - hf);
            g_Whi[idxs[q]] = hf;
            g_Wlo[idxs[q]] = __uint_as_float(lb);
        }
    }
}

// ---------------------------------------------------------------------------
// Kernel 2: tensor-core batched matvec with cross-iteration LDG prefetch.
// ---------------------------------------------------------------------------
struct Acc { float c0, c1, c2, c3, d0, d1, d2, d3; };

// Load (l1,l2) of the 4 patch pixels for patch index idx.
__device__ __forceinline__ void load_px(const float* __restrict__ x, int idx,
                                        float2* pre) {
    int b  = idx / Pc;
    int p  = idx - b * Pc;
    int ph = p / PWc;
    int pw = p - ph * PWc;
    const float* base = x + (((b * Hc) + ph) * Wc + pw) * 3;
#pragma unroll
    for (int n = 0; n < 4; n++) {
        int dy = n >> 1, dx = n & 1;
        const float* px = base + (dy * Wc + dx) * 3;
        pre[n] = make_float2(__ldg(px + 1), __ldg(px + 2));
    }
}

__global__ void __launch_bounds__(128, 6)
k_qcnn(const float* __restrict__ x, float* __restrict__ out) {
    __shared__ uint v_sm[NWARP][32][36];   // tf32 bits, [warp][patch][k], pad 36

    int tid  = threadIdx.x;
    int wrp  = tid >> 5;
    int lane = tid & 31;
    int g    = lane >> 2;     // fragment row group (0..7)
    int mm   = lane & 3;      // fragment col-in-group

    // --- A fragments: top 16 rows of Whi/Wlo, 4 K-tiles x 4 regs each ---
    uint Ah[4][4], Al[4][4];
    {
        const uint* whi = (const uint*)g_Whi;
        const uint* wlo = (const uint*)g_Wlo;
#pragma unroll
        for (int t = 0; t < 4; t++) {
            int r0 = g, r1 = g + 8;
            int c0 = t * 8 + mm, c1 = c0 + 4;
            Ah[t][0] = whi[r0 * 32 + c0];
            Ah[t][1] = whi[r1 * 32 + c0];
            Ah[t][2] = whi[r0 * 32 + c1];
            Ah[t][3] = whi[r1 * 32 + c1];
            Al[t][0] = wlo[r0 * 32 + c0];
            Al[t][1] = wlo[r1 * 32 + c0];
            Al[t][2] = wlo[r0 * 32 + c1];
            Al[t][3] = wlo[r1 * 32 + c1];
        }
    }

    // WHT destination role: g==0 -> z0 (from w), g==4 -> z1, g==2 -> z2, g==1 -> z3
    int comp = -1;
    if (g == 0) comp = 0;
    else if (g == 4) comp = 1;
    else if (g == 2) comp = 2;
    else if (g == 1) comp = 3;

    auto run_tile = [&](int nt, Acc& A) {
        uint Bh[4][2];
        const uint* vb = &v_sm[wrp][nt * 8 + g][0];
#pragma unroll
        for (int t = 0; t < 4; t++) {
            Bh[t][0] = vb[t * 8 + mm];
            Bh[t][1] = vb[t * 8 + mm + 4];
        }
        A.c0 = A.c1 = A.c2 = A.c3 = 0.f;
        A.d0 = A.d1 = A.d2 = A.d3 = 0.f;
#pragma unroll
        for (int t = 0; t < 4; t++) {
            int  src = (t + 2) & 3;
            uint sx  = (t >= 2) ? 0x80000000u : 0u;
            uint p0 = Bh[src][0] ^ sx, p1 = Bh[src][1] ^ sx;
            MMA_TF32(A.c0, A.c1, A.c2, A.c3,
                     Ah[t][0], Ah[t][1], Ah[t][2], Ah[t][3],
                     Bh[t][0], Bh[t][1]);
            MMA_TF32(A.d0, A.d1, A.d2, A.d3,
                     Ah[t][0], Ah[t][1], Ah[t][2], Ah[t][3],
                     p0, p1);
            MMA_TF32(A.c0, A.c1, A.c2, A.c3,
                     Al[t][0], Al[t][1], Al[t][2], Al[t][3],
                     Bh[t][0], Bh[t][1]);
            MMA_TF32(A.d0, A.d1, A.d2, A.d3,
                     Al[t][0], Al[t][1], Al[t][2], Al[t][3],
                     p0, p1);
        }
    };

    auto epilogue = [&](int nt, int Wi, const Acc& A) {
        float pa0 = fmaf(A.c0, A.c0, A.d0 * A.d0);   // state g,   col 2mm
        float pb0 = fmaf(A.c2, A.c2, A.d2 * A.d2);   // state g+8, col 2mm
        float pa1 = fmaf(A.c1, A.c1, A.d1 * A.d1);   // state g,   col 2mm+1
        float pb1 = fmaf(A.c3, A.c3, A.d3 * A.d3);   // state g+8, col 2mm+1

        float u0 = pa0 + pb0, w0 = pa0 - pb0;
        float u1 = pa1 + pb1, w1 = pa1 - pb1;

#pragma unroll
        for (int r = 0; r < 3; r++) {
            int m = 4 << r;
            float sg = (lane & m) ? -1.f : 1.f;
            float p;
            p = __shfl_xor_sync(0xffffffffu, u0, m); u0 = fmaf(sg, u0, p);
            p = __shfl_xor_sync(0xffffffffu, u1, m); u1 = fmaf(sg, u1, p);
            p = __shfl_xor_sync(0xffffffffu, w0, m); w0 = fmaf(sg, w0, p);
            p = __shfl_xor_sync(0xffffffffu, w1, m); w1 = fmaf(sg, w1, p);
        }

        if (comp >= 0) {
            float v0 = (comp == 0) ? w0 : u0;
            float v1 = (comp == 0) ? w1 : u1;
            int p0 = Wi * 32 + nt * 8 + 2 * mm;
            out[p0 * 4 + comp]       = v0;
            out[(p0 + 1) * 4 + comp] = v1;
        }
    };

    int WiBase = (blockIdx.x * NWARP + wrp) * TITER;
    float2 pre[4], nxt[4];
    if (WiBase < WTOT) load_px(x, WiBase * 32 + lane, pre);

#pragma unroll 1
    for (int it = 0; it < TITER; it++) {
        int Wi = WiBase + it;
        if (Wi >= WTOT) break;

        // ---- encode patch Wi*32 + lane from prefetched pixels ----
        {
            float  cth[NQ];
            float2 eph[NQ];
#pragma unroll
            for (int n = 0; n < NQ; n++) {
                float sb, cb, sp, cp;
                __sincosf(1.57079632679489662f * pre[n].x, &sb, &cb);
                __sincosf(3.14159265358979323f * pre[n].y, &sp, &cp);
                cth[n] = cb;
                eph[n] = make_float2(sb * cp, sb * sp);
            }
            float2 ab[4], cd[4];
            ab[0] = make_float2(cth[0] * cth[1], 0.f);
            ab[1] = make_float2(cth[0] * eph[1].x, cth[0] * eph[1].y);
            ab[2] = make_float2(eph[0].x * cth[1], eph[0].y * cth[1]);
            ab[3] = cmul(eph[0], eph[1]);
            cd[0] = make_float2(cth[2] * cth[3], 0.f);
            cd[1] = make_float2(cth[2] * eph[3].x, cth[2] * eph[3].y);
            cd[2] = make_float2(eph[2].x * cth[3], eph[2].y * cth[3]);
            cd[3] = cmul(eph[2], eph[3]);

            float2 psi[16];
#pragma unroll
            for (int i = 0; i < 4; i++)
#pragma unroll
                for (int j = 0; j < 4; j++)
                    psi[i * 4 + j] = cmul(ab[i], cd[j]);

            uint4* vrow = reinterpret_cast<uint4*>(&v_sm[wrp][lane][0]);
#pragma unroll
            for (int q = 0; q < 4; q++)
                vrow[q] = make_uint4(tf32cvt(psi[4*q].x),   tf32cvt(psi[4*q+1].x),
                                     tf32cvt(psi[4*q+2].x), tf32cvt(psi[4*q+3].x));
#pragma unroll
            for (int q = 0; q < 4; q++)
                vrow[4 + q] = make_uint4(tf32cvt(psi[4*q].y),   tf32cvt(psi[4*q+1].y),
                                         tf32cvt(psi[4*q+2].y), tf32cvt(psi[4*q+3].y));
        }
        __syncwarp();

        // ---- prefetch next iteration's pixels (latency hidden by nt-loop) ----
        {
            int WiN = (Wi + 1 < WTOT) ? (Wi + 1) : Wi;
            load_px(x, WiN * 32 + lane, nxt);
        }

        // ---- 2-deep pipelined nt-tiles ----
        Acc a0, a1;
        run_tile(0, a0);
        run_tile(1, a1);
        epilogue(0, Wi, a0);
        run_tile(2, a0);
        epilogue(1, Wi, a1);
        run_tile(3, a1);
        epilogue(2, Wi, a0);
        epilogue(3, Wi, a1);

        __syncwarp();
        pre[0] = nxt[0]; pre[1] = nxt[1]; pre[2] = nxt[2]; pre[3] = nxt[3];
    }
}

extern "C" void kernel_launch(void* const* d_in, const int* in_sizes, int n_in,
                              void* d_out, int out_size) {
    const float* x = (const float*)d_in[0];
    const float* w = (const float*)d_in[1];
    float* out = (float*)d_out;

    k_build_U<<<1, 256>>>(w);
    k_qcnn<<<NBLK, NWARP * 32>>>(x, out);
}